// round 13
// baseline (speedup 1.0000x reference)
#include <cuda_runtime.h>
#include <cuda_fp16.h>
#include <cstdint>

// ---------------------------------------------------------------------------
// SpatialCrossAttention — fp16 HMMA out-bmm + single-pass softmax attn
//   B=8, C=256, N=4096, DQK=16
//   out layout: [out1 | out2 | attention]
// ---------------------------------------------------------------------------

#define BATCH 8
#define CH    256
#define NPIX  4096
#define DQK   16
#define TWO_C 512

// SIMT GEMM tiling (v projection)
#define BM 128
#define BN 128
#define TK 16
#define PAD 4

// ---- device scratch ----
__device__ float  g_q[BATCH * DQK * NPIX];
__device__ float  g_k[BATCH * DQK * NPIX];
__device__ __half g_v_h[2][BATCH * CH * NPIX];            // 32 MB
__device__ __half g_att_h[(size_t)BATCH * NPIX * NPIX];   // 256 MB

// ===========================================================================
// helpers
// ===========================================================================
__device__ __forceinline__ uint32_t smem_u32(const void* p) {
    uint32_t a;
    asm("{ .reg .u64 t; cvta.to.shared.u64 t, %1; cvt.u32.u64 %0, t; }" : "=r"(a) : "l"(p));
    return a;
}

__device__ __forceinline__ uint32_t pack_h2(float lo, float hi) {
    __half2 h = __floats2half2_rn(lo, hi);
    return *(uint32_t*)&h;
}

#define CP_ASYNC16(dst, src) \
    asm volatile("cp.async.cg.shared.global [%0], [%1], 16;" :: "r"(dst), "l"(src) : "memory")
#define CP_COMMIT() asm volatile("cp.async.commit_group;" ::: "memory")
#define CP_WAIT2()  asm volatile("cp.async.wait_group 2;" ::: "memory")
#define CP_WAIT0()  asm volatile("cp.async.wait_group 0;" ::: "memory")

#define LDSM_X4(r0, r1, r2, r3, addr) \
    asm volatile("ldmatrix.sync.aligned.m8n8.x4.shared.b16 {%0,%1,%2,%3}, [%4];" \
                 : "=r"(r0), "=r"(r1), "=r"(r2), "=r"(r3) : "r"(addr))

__device__ __forceinline__ void mma_f16(float* c, const uint32_t* a, const uint32_t* b) {
    asm volatile(
        "mma.sync.aligned.m16n8k16.row.col.f32.f16.f16.f32 "
        "{%0,%1,%2,%3}, {%4,%5,%6,%7}, {%8,%9}, {%0,%1,%2,%3};"
        : "+f"(c[0]), "+f"(c[1]), "+f"(c[2]), "+f"(c[3])
        : "r"(a[0]), "r"(a[1]), "r"(a[2]), "r"(a[3]), "r"(b[0]), "r"(b[1]));
}

// ===========================================================================
// Kernel 1: q/k projection
// ===========================================================================
__global__ __launch_bounds__(256) void qk_kernel(
    const float* __restrict__ x1, const float* __restrict__ x2,
    const float* __restrict__ Wq, const float* __restrict__ bq,
    const float* __restrict__ Wk, const float* __restrict__ bk)
{
    __shared__ float xs[64][33];
    __shared__ float wqs[16][64];
    __shared__ float wks[16][64];

    const int n0  = blockIdx.x * 32;
    const int b   = blockIdx.y;
    const int tid = threadIdx.x;
    const int nl  = tid & 31;
    const int dg  = tid >> 5;

    float aq0 = 0.f, aq1 = 0.f, ak0 = 0.f, ak1 = 0.f;

    for (int c0 = 0; c0 < TWO_C; c0 += 64) {
        for (int r = dg; r < 64; r += 8) {
            const int c = c0 + r;
            const float* src = (c < CH) ? x1 : x2;
            xs[r][nl] = src[((size_t)b * CH + (c & (CH - 1))) * NPIX + n0 + nl];
        }
        for (int i = tid; i < 16 * 64; i += 256) {
            const int d = i >> 6, cc = i & 63;
            wqs[d][cc] = Wq[d * TWO_C + c0 + cc];
            wks[d][cc] = Wk[d * TWO_C + c0 + cc];
        }
        __syncthreads();
        #pragma unroll
        for (int cc = 0; cc < 64; cc++) {
            const float xv = xs[cc][nl];
            aq0 = fmaf(wqs[dg    ][cc], xv, aq0);
            aq1 = fmaf(wqs[dg + 8][cc], xv, aq1);
            ak0 = fmaf(wks[dg    ][cc], xv, ak0);
            ak1 = fmaf(wks[dg + 8][cc], xv, ak1);
        }
        __syncthreads();
    }

    const size_t base = (size_t)b * DQK * NPIX + n0 + nl;
    g_q[base + (size_t)(dg    ) * NPIX] = aq0 + bq[dg];
    g_q[base + (size_t)(dg + 8) * NPIX] = aq1 + bq[dg + 8];
    g_k[base + (size_t)(dg    ) * NPIX] = ak0 + bk[dg];
    g_k[base + (size_t)(dg + 8) * NPIX] = ak1 + bk[dg + 8];
}

// ===========================================================================
// Kernel 2: v projection GEMM (SIMT fp32; epilogue stores V as fp16)
// ===========================================================================
__global__ __launch_bounds__(256, 2) void v_gemm_kernel(
    const float* __restrict__ x1, const float* __restrict__ x2,
    const float* __restrict__ Wv1, const float* __restrict__ bv1,
    const float* __restrict__ Wv2, const float* __restrict__ bv2)
{
    __shared__ float As[2][TK][BM + PAD];
    __shared__ float Bs[2][TK][BN + PAD];

    const int which = blockIdx.z & 1;
    const int b     = blockIdx.z >> 1;
    const float* __restrict__ Wv = which ? Wv2 : Wv1;
    const float* __restrict__ bv = which ? bv2 : bv1;
    const float* __restrict__ Xb = (which ? x2 : x1) + (size_t)b * CH * NPIX;
    __half* __restrict__ V       = g_v_h[which] + (size_t)b * CH * NPIX;

    const int n0  = blockIdx.x * BN;
    const int o0  = blockIdx.y * BM;
    const int tid = threadIdx.x;
    const int tx  = tid & 15, ty = tid >> 4;

    const int ar  = tid >> 2;
    const int ak  = (tid & 3) << 2;
    const int bkr = tid >> 5;
    const int bj  = (tid & 31) << 2;

    float acc[8][8];
    #pragma unroll
    for (int r = 0; r < 8; r++)
        #pragma unroll
        for (int s = 0; s < 8; s++) acc[r][s] = 0.f;

    const int KT = CH / TK;
    float4 a0n, a1n, b0n, b1n;

    {
        const float* ap = Wv + (o0 + ar) * CH + ak;
        a0n = *(const float4*)ap;
        a1n = *(const float4*)(ap + 64 * CH);
        const float* bp = Xb + (size_t)bkr * NPIX + n0 + bj;
        b0n = *(const float4*)bp;
        b1n = *(const float4*)(bp + (size_t)8 * NPIX);
        As[0][ak + 0][ar] = a0n.x; As[0][ak + 1][ar] = a0n.y;
        As[0][ak + 2][ar] = a0n.z; As[0][ak + 3][ar] = a0n.w;
        As[0][ak + 0][ar + 64] = a1n.x; As[0][ak + 1][ar + 64] = a1n.y;
        As[0][ak + 2][ar + 64] = a1n.z; As[0][ak + 3][ar + 64] = a1n.w;
        *(float4*)&Bs[0][bkr    ][bj] = b0n;
        *(float4*)&Bs[0][bkr + 8][bj] = b1n;
    }
    __syncthreads();

    for (int kt = 0; kt < KT; kt++) {
        const int cur = kt & 1;
        const bool pf = (kt + 1 < KT);
        if (pf) {
            const int kc = (kt + 1) * TK;
            const float* ap = Wv + (o0 + ar) * CH + kc + ak;
            a0n = *(const float4*)ap;
            a1n = *(const float4*)(ap + 64 * CH);
            const float* bp = Xb + (size_t)(kc + bkr) * NPIX + n0 + bj;
            b0n = *(const float4*)bp;
            b1n = *(const float4*)(bp + (size_t)8 * NPIX);
        }
        #pragma unroll
        for (int k = 0; k < TK; k++) {
            const float4 a0 = *(const float4*)&As[cur][k][ty * 4];
            const float4 a1 = *(const float4*)&As[cur][k][64 + ty * 4];
            const float4 b0 = *(const float4*)&Bs[cur][k][tx * 4];
            const float4 b1 = *(const float4*)&Bs[cur][k][64 + tx * 4];
            const float av[8] = {a0.x, a0.y, a0.z, a0.w, a1.x, a1.y, a1.z, a1.w};
            const float bw[8] = {b0.x, b0.y, b0.z, b0.w, b1.x, b1.y, b1.z, b1.w};
            #pragma unroll
            for (int r = 0; r < 8; r++)
                #pragma unroll
                for (int s = 0; s < 8; s++)
                    acc[r][s] = fmaf(av[r], bw[s], acc[r][s]);
        }
        if (pf) {
            const int nb = cur ^ 1;
            As[nb][ak + 0][ar] = a0n.x; As[nb][ak + 1][ar] = a0n.y;
            As[nb][ak + 2][ar] = a0n.z; As[nb][ak + 3][ar] = a0n.w;
            As[nb][ak + 0][ar + 64] = a1n.x; As[nb][ak + 1][ar + 64] = a1n.y;
            As[nb][ak + 2][ar + 64] = a1n.z; As[nb][ak + 3][ar + 64] = a1n.w;
            *(float4*)&Bs[nb][bkr    ][bj] = b0n;
            *(float4*)&Bs[nb][bkr + 8][bj] = b1n;
        }
        __syncthreads();
    }

    #pragma unroll
    for (int rg = 0; rg < 2; rg++)
        #pragma unroll
        for (int rr = 0; rr < 4; rr++) {
            const int r = rg * 4 + rr;
            const int o = o0 + rg * 64 + ty * 4 + rr;
            const float bias = __ldg(&bv[o]);
            __half* dst = V + (size_t)o * NPIX + n0;
            uint2 h0, h1;
            h0.x = pack_h2(acc[r][0] + bias, acc[r][1] + bias);
            h0.y = pack_h2(acc[r][2] + bias, acc[r][3] + bias);
            h1.x = pack_h2(acc[r][4] + bias, acc[r][5] + bias);
            h1.y = pack_h2(acc[r][6] + bias, acc[r][7] + bias);
            *(uint2*)(dst + tx * 4)      = h0;
            *(uint2*)(dst + 64 + tx * 4) = h1;
        }
}

// ===========================================================================
// Kernel 3: SINGLE-PASS energy + softmax.
//   Block owns 16 query rows. p = exp(e) (no max needed: |e| <~ 6) buffered
//   in smem fp16 [16][4096] (128 KB); one k-stream; then normalized writeback
//   to fp32 att (d_out) and fp16 att (GEMM scratch).
//   Dynamic smem: ph 131072 B + ks 16384 B = 147456 B.
// ===========================================================================
#define AROWS 16
#define ATT_SMEM (AROWS * NPIX * 2 + 16 * 256 * 4)

__global__ __launch_bounds__(256) void attn_kernel(float* __restrict__ att)
{
    extern __shared__ char asmem[];
    __half* __restrict__ ph = (__half*)asmem;                      // [16][4096]
    float*  __restrict__ ks = (float*)(asmem + AROWS * NPIX * 2);  // [16][256]
    __shared__ float qs[DQK][AROWS];
    __shared__ float s_inv[AROWS];

    const int n0   = blockIdx.x * AROWS;
    const int b    = blockIdx.y;
    const int tid  = threadIdx.x;
    const int lane = tid & 31;
    const int w    = tid >> 5;
    const int r0   = 2 * w;        // warp handles rows r0, r0+1

    const float* __restrict__ qb = g_q + (size_t)b * DQK * NPIX;
    const float* __restrict__ kb = g_k + (size_t)b * DQK * NPIX;
    float* __restrict__ attb     = att + (size_t)b * NPIX * NPIX;
    __half* __restrict__ atth    = g_att_h + (size_t)b * NPIX * NPIX;

    // stage q (16 d x 16 rows), hoist to registers
    qs[tid >> 4][tid & 15] = qb[(size_t)(tid >> 4) * NPIX + n0 + (tid & 15)];
    __syncthreads();
    float qr0[DQK], qr1[DQK];
    #pragma unroll
    for (int d = 0; d < DQK; d++) { qr0[d] = qs[d][r0]; qr1[d] = qs[d][r0 + 1]; }

    float sum0 = 0.f, sum1 = 0.f;

    for (int m0 = 0; m0 < NPIX; m0 += 256) {
        __syncthreads();
        #pragma unroll
        for (int r = 0; r < 4; r++) {
            const int lin = tid + 256 * r;
            const int d = lin >> 6, mm4 = (lin & 63) << 2;
            *(float4*)&ks[d * 256 + mm4] = *(const float4*)&kb[(size_t)d * NPIX + m0 + mm4];
        }
        __syncthreads();
        #pragma unroll
        for (int it = 0; it < 4; it++) {
            const int mm = 64 * it + 2 * lane;    // pair of adjacent m
            float e00 = 0.f, e01 = 0.f, e10 = 0.f, e11 = 0.f;
            #pragma unroll
            for (int d = 0; d < DQK; d++) {
                const float2 k2 = *(const float2*)&ks[d * 256 + mm];
                e00 = fmaf(qr0[d], k2.x, e00);
                e01 = fmaf(qr0[d], k2.y, e01);
                e10 = fmaf(qr1[d], k2.x, e10);
                e11 = fmaf(qr1[d], k2.y, e11);
            }
            const float p00 = __expf(e00), p01 = __expf(e01);
            const float p10 = __expf(e10), p11 = __expf(e11);
            sum0 += p00 + p01;
            sum1 += p10 + p11;
            *(__half2*)&ph[(size_t)r0 * NPIX + m0 + mm]       = __floats2half2_rn(p00, p01);
            *(__half2*)&ph[(size_t)(r0 + 1) * NPIX + m0 + mm] = __floats2half2_rn(p10, p11);
        }
    }

    // warp-reduce row sums
    #pragma unroll
    for (int off = 16; off; off >>= 1) {
        sum0 += __shfl_xor_sync(0xffffffffu, sum0, off);
        sum1 += __shfl_xor_sync(0xffffffffu, sum1, off);
    }
    if (lane == 0) { s_inv[r0] = 1.f / sum0; s_inv[r0 + 1] = 1.f / sum1; }
    __syncthreads();

    // writeback: normalized fp32 att + fp16 att
    for (int r = 0; r < AROWS; r++) {
        const float inv = s_inv[r];
        const __half* src = ph + (size_t)r * NPIX;
        float* dstF  = attb + (size_t)(n0 + r) * NPIX;
        __half* dstH = atth + (size_t)(n0 + r) * NPIX;
        #pragma unroll
        for (int j = 0; j < 8; j++) {
            const int col = 2 * tid + 512 * j;
            const __half2 h2 = *(const __half2*)&src[col];
            const float2 p = __half22float2(h2);
            float2 o;
            o.x = p.x * inv;
            o.y = p.y * inv;
            *(float2*)&dstF[col] = o;
            *(__half2*)&dstH[col] = __floats2half2_rn(o.x, o.y);
        }
    }
}

// ===========================================================================
// Kernel 4: out-bmm via fp16 HMMA m16n8k16 + ldmatrix, 16 warps/CTA.
//   (unchanged from R12 passing version)
// ===========================================================================
#define HBM_ 128
#define HBN_ 256
#define HBK_ 32
#define H_A_BYTES (HBM_ * 64)                    // 8192
#define H_STAGE   ((HBM_ + HBN_) * 64)           // 24576
#define HNSTAGE   4
#define HSMEM     (HNSTAGE * H_STAGE)            // 98304

__global__ __launch_bounds__(512, 1) void out_gemm_h(
    const float* __restrict__ x1, const float* __restrict__ x2,
    float* __restrict__ out)
{
    extern __shared__ char smraw[];
    const uint32_t smb = smem_u32(smraw);

    const int tid  = threadIdx.x;
    const int wid  = tid >> 5;     // 0..15
    const int lane = tid & 31;
    const int grp  = lane >> 2;
    const int tig  = lane & 3;
    const int wm   = wid >> 2;     // 0..3 -> m offset 32*wm
    const int wn   = wid & 3;      // 0..3 -> n offset 64*wn

    const int which = blockIdx.z & 1;
    const int b     = blockIdx.z >> 1;
    const int n0    = blockIdx.x * HBN_;
    const int c0    = blockIdx.y * HBM_;

    const __half* __restrict__ Vb = g_v_h[which] + (size_t)b * CH * NPIX;
    const __half* __restrict__ Ah = g_att_h + (size_t)b * NPIX * NPIX;

    // ---- producer mapping (swizzled 16B chunks), 512 threads ----
    const int a_row = tid >> 2;
    const int a_j   = tid & 3;
    const uint32_t aDst = smb + (uint32_t)(a_row * 64 + ((a_j ^ ((a_row >> 1) & 3)) * 16));
    const __half* aSrc = Vb + (size_t)(c0 + a_row) * NPIX + a_j * 8;
    const int b_row = tid >> 1;
    const int b_j0  = (tid & 1) * 2;
    const int b_sw  = (b_row >> 1) & 3;
    uint32_t bDst[2];
    #pragma unroll
    for (int i = 0; i < 2; i++)
        bDst[i] = smb + (uint32_t)(H_A_BYTES + b_row * 64 + (((b_j0 + i) ^ b_sw) * 16));
    const __half* bSrc = Ah + (size_t)(n0 + b_row) * NPIX + b_j0 * 8;

    // ---- ldmatrix lane constants ----
    const int radd = lane & 15;
    const int jA   = lane >> 4;
    const int lsw  = (radd >> 1) & 3;
    const uint32_t rowOff = (uint32_t)radd * 64;
    uint32_t cswk[2];
    cswk[0] = (uint32_t)(((0 + jA) ^ lsw) * 16);
    cswk[1] = (uint32_t)(((2 + jA) ^ lsw) * 16);

    float acc[2][8][4];
    #pragma unroll
    for (int mt = 0; mt < 2; mt++)
        #pragma unroll
        for (int nt = 0; nt < 8; nt++)
            #pragma unroll
            for (int q = 0; q < 4; q++) acc[mt][nt][q] = 0.f;

    const int KT = NPIX / HBK_;   // 128

    #pragma unroll
    for (int s = 0; s < HNSTAGE - 1; s++) {
        const uint32_t so = (uint32_t)(s * H_STAGE);
        const int kc = s * HBK_;
        CP_ASYNC16(aDst + so, aSrc + kc);
        #pragma unroll
        for (int i = 0; i < 2; i++) CP_ASYNC16(bDst[i] + so, bSrc + kc + i * 8);
        CP_COMMIT();
    }

    const uint32_t aWarp = smb + (uint32_t)(wm * 32) * 64 + rowOff;
    const uint32_t bWarp = smb + H_A_BYTES + (uint32_t)(wn * 64) * 64 + rowOff;

    for (int kt = 0; kt < KT; kt++) {
        CP_WAIT2();
        __syncthreads();

        const int nk = kt + HNSTAGE - 1;
        if (nk < KT) {
            const uint32_t so = (uint32_t)((nk & (HNSTAGE - 1)) * H_STAGE);
            const int kc = nk * HBK_;
            CP_ASYNC16(aDst + so, aSrc + kc);
            #pragma unroll
            for (int i = 0; i < 2; i++) CP_ASYNC16(bDst[i] + so, bSrc + kc + i * 8);
        }
        CP_COMMIT();

        const uint32_t so = (uint32_t)((kt & (HNSTAGE - 1)) * H_STAGE);
        const uint32_t aB = aWarp + so;
        const uint32_t bB = bWarp + so;

        #pragma unroll
        for (int ksp = 0; ksp < 2; ksp++) {
            uint32_t af[2][4];
            #pragma unroll
            for (int mt = 0; mt < 2; mt++)
                LDSM_X4(af[mt][0], af[mt][1], af[mt][2], af[mt][3],
                        aB + (uint32_t)(mt * 1024) + cswk[ksp]);
            uint32_t bf[8][2];
            #pragma unroll
            for (int ntp = 0; ntp < 4; ntp++) {
                uint32_t q0, q1, q2, q3;
                LDSM_X4(q0, q1, q2, q3, bB + (uint32_t)(ntp * 1024) + cswk[ksp]);
                bf[2 * ntp    ][0] = q0; bf[2 * ntp    ][1] = q2;
                bf[2 * ntp + 1][0] = q1; bf[2 * ntp + 1][1] = q3;
            }
            #pragma unroll
            for (int mt = 0; mt < 2; mt++)
                #pragma unroll
                for (int nt = 0; nt < 8; nt++)
                    mma_f16(acc[mt][nt], af[mt], bf[nt]);
        }
        __syncthreads();
    }
    CP_WAIT0();

    // ---- epilogue: + residual x (fp32), store ----
    const float* __restrict__ Xb = (which ? x2 : x1) + (size_t)b * CH * NPIX;
    float* __restrict__ Ob = out + (size_t)which * BATCH * CH * NPIX + (size_t)b * CH * NPIX;

    #pragma unroll
    for (int mt = 0; mt < 2; mt++) {
        const int row0 = c0 + wm * 32 + mt * 16 + grp;
        const size_t r0b = (size_t)row0 * NPIX;
        const size_t r1b = (size_t)(row0 + 8) * NPIX;
        #pragma unroll
        for (int nt = 0; nt < 8; nt++) {
            const int col = n0 + wn * 64 + nt * 8 + tig * 2;
            const float2 x0 = *(const float2*)&Xb[r0b + col];
            const float2 x1v = *(const float2*)&Xb[r1b + col];
            float2 o0, o1;
            o0.x = acc[mt][nt][0] + x0.x;  o0.y = acc[mt][nt][1] + x0.y;
            o1.x = acc[mt][nt][2] + x1v.x; o1.y = acc[mt][nt][3] + x1v.y;
            *(float2*)&Ob[r0b + col] = o0;
            *(float2*)&Ob[r1b + col] = o1;
        }
    }
}

// ===========================================================================
// launch
// ===========================================================================
extern "C" void kernel_launch(void* const* d_in, const int* in_sizes, int n_in,
                              void* d_out, int out_size)
{
    (void)in_sizes; (void)n_in; (void)out_size;
    const float* x1  = (const float*)d_in[0];
    const float* x2  = (const float*)d_in[1];
    const float* Wq  = (const float*)d_in[2];
    const float* bq  = (const float*)d_in[3];
    const float* Wk  = (const float*)d_in[4];
    const float* bk  = (const float*)d_in[5];
    const float* Wv1 = (const float*)d_in[6];
    const float* bv1 = (const float*)d_in[7];
    const float* Wv2 = (const float*)d_in[8];
    const float* bv2 = (const float*)d_in[9];

    float* out = (float*)d_out;
    float* att = out + (size_t)2 * BATCH * CH * NPIX;

    cudaFuncSetAttribute(out_gemm_h, cudaFuncAttributeMaxDynamicSharedMemorySize, HSMEM);
    cudaFuncSetAttribute(attn_kernel, cudaFuncAttributeMaxDynamicSharedMemorySize, ATT_SMEM);

    qk_kernel<<<dim3(NPIX / 32, BATCH), 256>>>(x1, x2, Wq, bq, Wk, bk);
    v_gemm_kernel<<<dim3(NPIX / BN, CH / BM, BATCH * 2), 256>>>(x1, x2, Wv1, bv1, Wv2, bv2);
    attn_kernel<<<dim3(NPIX / AROWS, BATCH), 256, ATT_SMEM>>>(att);
    out_gemm_h<<<dim3(NPIX / HBN_, CH / HBM_, BATCH * 2), 512, HSMEM>>>(x1, x2, out);
}

// round 14
// speedup vs baseline: 1.0682x; 1.0682x over previous
#include <cuda_runtime.h>
#include <cuda_fp16.h>
#include <cstdint>

// ---------------------------------------------------------------------------
// SpatialCrossAttention — fp16 HMMA out-bmm (128x128 blocks, 2 CTAs/SM)
//   B=8, C=256, N=4096, DQK=16
//   out layout: [out1 | out2 | attention]
// ---------------------------------------------------------------------------

#define BATCH 8
#define CH    256
#define NPIX  4096
#define DQK   16
#define TWO_C 512

// SIMT GEMM tiling (v projection)
#define BM 128
#define BN 128
#define TK 16
#define PAD 4

// ---- device scratch ----
__device__ float  g_q[BATCH * DQK * NPIX];
__device__ float  g_k[BATCH * DQK * NPIX];
__device__ __half g_v_h[2][BATCH * CH * NPIX];            // 32 MB
__device__ __half g_att_h[(size_t)BATCH * NPIX * NPIX];   // 256 MB

// ===========================================================================
// helpers
// ===========================================================================
__device__ __forceinline__ uint32_t smem_u32(const void* p) {
    uint32_t a;
    asm("{ .reg .u64 t; cvta.to.shared.u64 t, %1; cvt.u32.u64 %0, t; }" : "=r"(a) : "l"(p));
    return a;
}

__device__ __forceinline__ uint32_t pack_h2(float lo, float hi) {
    __half2 h = __floats2half2_rn(lo, hi);
    return *(uint32_t*)&h;
}

#define CP_ASYNC16(dst, src) \
    asm volatile("cp.async.cg.shared.global [%0], [%1], 16;" :: "r"(dst), "l"(src) : "memory")
#define CP_COMMIT() asm volatile("cp.async.commit_group;" ::: "memory")
#define CP_WAIT2()  asm volatile("cp.async.wait_group 2;" ::: "memory")
#define CP_WAIT0()  asm volatile("cp.async.wait_group 0;" ::: "memory")

#define LDSM_X4(r0, r1, r2, r3, addr) \
    asm volatile("ldmatrix.sync.aligned.m8n8.x4.shared.b16 {%0,%1,%2,%3}, [%4];" \
                 : "=r"(r0), "=r"(r1), "=r"(r2), "=r"(r3) : "r"(addr))

__device__ __forceinline__ void mma_f16(float* c, const uint32_t* a, const uint32_t* b) {
    asm volatile(
        "mma.sync.aligned.m16n8k16.row.col.f32.f16.f16.f32 "
        "{%0,%1,%2,%3}, {%4,%5,%6,%7}, {%8,%9}, {%0,%1,%2,%3};"
        : "+f"(c[0]), "+f"(c[1]), "+f"(c[2]), "+f"(c[3])
        : "r"(a[0]), "r"(a[1]), "r"(a[2]), "r"(a[3]), "r"(b[0]), "r"(b[1]));
}

// ===========================================================================
// Kernel 1: q/k projection
// ===========================================================================
__global__ __launch_bounds__(256) void qk_kernel(
    const float* __restrict__ x1, const float* __restrict__ x2,
    const float* __restrict__ Wq, const float* __restrict__ bq,
    const float* __restrict__ Wk, const float* __restrict__ bk)
{
    __shared__ float xs[64][33];
    __shared__ float wqs[16][64];
    __shared__ float wks[16][64];

    const int n0  = blockIdx.x * 32;
    const int b   = blockIdx.y;
    const int tid = threadIdx.x;
    const int nl  = tid & 31;
    const int dg  = tid >> 5;

    float aq0 = 0.f, aq1 = 0.f, ak0 = 0.f, ak1 = 0.f;

    for (int c0 = 0; c0 < TWO_C; c0 += 64) {
        for (int r = dg; r < 64; r += 8) {
            const int c = c0 + r;
            const float* src = (c < CH) ? x1 : x2;
            xs[r][nl] = src[((size_t)b * CH + (c & (CH - 1))) * NPIX + n0 + nl];
        }
        for (int i = tid; i < 16 * 64; i += 256) {
            const int d = i >> 6, cc = i & 63;
            wqs[d][cc] = Wq[d * TWO_C + c0 + cc];
            wks[d][cc] = Wk[d * TWO_C + c0 + cc];
        }
        __syncthreads();
        #pragma unroll
        for (int cc = 0; cc < 64; cc++) {
            const float xv = xs[cc][nl];
            aq0 = fmaf(wqs[dg    ][cc], xv, aq0);
            aq1 = fmaf(wqs[dg + 8][cc], xv, aq1);
            ak0 = fmaf(wks[dg    ][cc], xv, ak0);
            ak1 = fmaf(wks[dg + 8][cc], xv, ak1);
        }
        __syncthreads();
    }

    const size_t base = (size_t)b * DQK * NPIX + n0 + nl;
    g_q[base + (size_t)(dg    ) * NPIX] = aq0 + bq[dg];
    g_q[base + (size_t)(dg + 8) * NPIX] = aq1 + bq[dg + 8];
    g_k[base + (size_t)(dg    ) * NPIX] = ak0 + bk[dg];
    g_k[base + (size_t)(dg + 8) * NPIX] = ak1 + bk[dg + 8];
}

// ===========================================================================
// Kernel 2: v projection GEMM (SIMT fp32; epilogue stores V as fp16)
// ===========================================================================
__global__ __launch_bounds__(256, 2) void v_gemm_kernel(
    const float* __restrict__ x1, const float* __restrict__ x2,
    const float* __restrict__ Wv1, const float* __restrict__ bv1,
    const float* __restrict__ Wv2, const float* __restrict__ bv2)
{
    __shared__ float As[2][TK][BM + PAD];
    __shared__ float Bs[2][TK][BN + PAD];

    const int which = blockIdx.z & 1;
    const int b     = blockIdx.z >> 1;
    const float* __restrict__ Wv = which ? Wv2 : Wv1;
    const float* __restrict__ bv = which ? bv2 : bv1;
    const float* __restrict__ Xb = (which ? x2 : x1) + (size_t)b * CH * NPIX;
    __half* __restrict__ V       = g_v_h[which] + (size_t)b * CH * NPIX;

    const int n0  = blockIdx.x * BN;
    const int o0  = blockIdx.y * BM;
    const int tid = threadIdx.x;
    const int tx  = tid & 15, ty = tid >> 4;

    const int ar  = tid >> 2;
    const int ak  = (tid & 3) << 2;
    const int bkr = tid >> 5;
    const int bj  = (tid & 31) << 2;

    float acc[8][8];
    #pragma unroll
    for (int r = 0; r < 8; r++)
        #pragma unroll
        for (int s = 0; s < 8; s++) acc[r][s] = 0.f;

    const int KT = CH / TK;
    float4 a0n, a1n, b0n, b1n;

    {
        const float* ap = Wv + (o0 + ar) * CH + ak;
        a0n = *(const float4*)ap;
        a1n = *(const float4*)(ap + 64 * CH);
        const float* bp = Xb + (size_t)bkr * NPIX + n0 + bj;
        b0n = *(const float4*)bp;
        b1n = *(const float4*)(bp + (size_t)8 * NPIX);
        As[0][ak + 0][ar] = a0n.x; As[0][ak + 1][ar] = a0n.y;
        As[0][ak + 2][ar] = a0n.z; As[0][ak + 3][ar] = a0n.w;
        As[0][ak + 0][ar + 64] = a1n.x; As[0][ak + 1][ar + 64] = a1n.y;
        As[0][ak + 2][ar + 64] = a1n.z; As[0][ak + 3][ar + 64] = a1n.w;
        *(float4*)&Bs[0][bkr    ][bj] = b0n;
        *(float4*)&Bs[0][bkr + 8][bj] = b1n;
    }
    __syncthreads();

    for (int kt = 0; kt < KT; kt++) {
        const int cur = kt & 1;
        const bool pf = (kt + 1 < KT);
        if (pf) {
            const int kc = (kt + 1) * TK;
            const float* ap = Wv + (o0 + ar) * CH + kc + ak;
            a0n = *(const float4*)ap;
            a1n = *(const float4*)(ap + 64 * CH);
            const float* bp = Xb + (size_t)(kc + bkr) * NPIX + n0 + bj;
            b0n = *(const float4*)bp;
            b1n = *(const float4*)(bp + (size_t)8 * NPIX);
        }
        #pragma unroll
        for (int k = 0; k < TK; k++) {
            const float4 a0 = *(const float4*)&As[cur][k][ty * 4];
            const float4 a1 = *(const float4*)&As[cur][k][64 + ty * 4];
            const float4 b0 = *(const float4*)&Bs[cur][k][tx * 4];
            const float4 b1 = *(const float4*)&Bs[cur][k][64 + tx * 4];
            const float av[8] = {a0.x, a0.y, a0.z, a0.w, a1.x, a1.y, a1.z, a1.w};
            const float bw[8] = {b0.x, b0.y, b0.z, b0.w, b1.x, b1.y, b1.z, b1.w};
            #pragma unroll
            for (int r = 0; r < 8; r++)
                #pragma unroll
                for (int s = 0; s < 8; s++)
                    acc[r][s] = fmaf(av[r], bw[s], acc[r][s]);
        }
        if (pf) {
            const int nb = cur ^ 1;
            As[nb][ak + 0][ar] = a0n.x; As[nb][ak + 1][ar] = a0n.y;
            As[nb][ak + 2][ar] = a0n.z; As[nb][ak + 3][ar] = a0n.w;
            As[nb][ak + 0][ar + 64] = a1n.x; As[nb][ak + 1][ar + 64] = a1n.y;
            As[nb][ak + 2][ar + 64] = a1n.z; As[nb][ak + 3][ar + 64] = a1n.w;
            *(float4*)&Bs[nb][bkr    ][bj] = b0n;
            *(float4*)&Bs[nb][bkr + 8][bj] = b1n;
        }
        __syncthreads();
    }

    #pragma unroll
    for (int rg = 0; rg < 2; rg++)
        #pragma unroll
        for (int rr = 0; rr < 4; rr++) {
            const int r = rg * 4 + rr;
            const int o = o0 + rg * 64 + ty * 4 + rr;
            const float bias = __ldg(&bv[o]);
            __half* dst = V + (size_t)o * NPIX + n0;
            uint2 h0, h1;
            h0.x = pack_h2(acc[r][0] + bias, acc[r][1] + bias);
            h0.y = pack_h2(acc[r][2] + bias, acc[r][3] + bias);
            h1.x = pack_h2(acc[r][4] + bias, acc[r][5] + bias);
            h1.y = pack_h2(acc[r][6] + bias, acc[r][7] + bias);
            *(uint2*)(dst + tx * 4)      = h0;
            *(uint2*)(dst + 64 + tx * 4) = h1;
        }
}

// ===========================================================================
// Kernel 3: energy + softmax -> fp32 attention (d_out) + fp16 copy (scratch)
//   (two-pass version — reverted from R13's single-pass regression)
// ===========================================================================
__global__ __launch_bounds__(256) void attn_kernel(float* __restrict__ att)
{
    __shared__ float ks[16][256];
    __shared__ float qs[16][32];
    __shared__ float s_mx[32];
    __shared__ float s_inv[32];

    const int n0   = blockIdx.x * 32;
    const int b    = blockIdx.y;
    const int tid  = threadIdx.x;
    const int lane = tid & 31;
    const int w    = tid >> 5;
    const int rb   = w * 4;

    const float* __restrict__ qb = g_q + (size_t)b * DQK * NPIX;
    const float* __restrict__ kb = g_k + (size_t)b * DQK * NPIX;
    float* __restrict__ attb     = att + (size_t)b * NPIX * NPIX;
    __half* __restrict__ atth    = g_att_h + (size_t)b * NPIX * NPIX;

    for (int i = tid; i < 512; i += 256) {
        const int d = i >> 5, nl = i & 31;
        qs[d][nl] = qb[(size_t)d * NPIX + n0 + nl];
    }
    __syncthreads();
    float qr[4][16];
    #pragma unroll
    for (int rr = 0; rr < 4; rr++)
        #pragma unroll
        for (int d = 0; d < 16; d++)
            qr[rr][d] = qs[d][rb + rr];

    float mx[4], sm[4];
    #pragma unroll
    for (int rr = 0; rr < 4; rr++) { mx[rr] = -1e30f; sm[rr] = 0.f; }

    for (int m0 = 0; m0 < NPIX; m0 += 256) {
        __syncthreads();
        #pragma unroll
        for (int r = 0; r < 4; r++) {
            const int lin = tid + 256 * r;
            const int d = lin >> 6, mm4 = (lin & 63) << 2;
            *(float4*)&ks[d][mm4] = *(const float4*)&kb[(size_t)d * NPIX + m0 + mm4];
        }
        __syncthreads();
        #pragma unroll
        for (int it = 0; it < 8; it++) {
            const int mm = lane + it * 32;
            float e0 = 0.f, e1 = 0.f, e2 = 0.f, e3 = 0.f;
            #pragma unroll
            for (int d = 0; d < 16; d++) {
                const float kv = ks[d][mm];
                e0 = fmaf(qr[0][d], kv, e0);
                e1 = fmaf(qr[1][d], kv, e1);
                e2 = fmaf(qr[2][d], kv, e2);
                e3 = fmaf(qr[3][d], kv, e3);
            }
            { const float dd = e0 - mx[0]; if (dd > 0.f) { sm[0] = sm[0] * __expf(-dd) + 1.f; mx[0] = e0; } else sm[0] += __expf(dd); }
            { const float dd = e1 - mx[1]; if (dd > 0.f) { sm[1] = sm[1] * __expf(-dd) + 1.f; mx[1] = e1; } else sm[1] += __expf(dd); }
            { const float dd = e2 - mx[2]; if (dd > 0.f) { sm[2] = sm[2] * __expf(-dd) + 1.f; mx[2] = e2; } else sm[2] += __expf(dd); }
            { const float dd = e3 - mx[3]; if (dd > 0.f) { sm[3] = sm[3] * __expf(-dd) + 1.f; mx[3] = e3; } else sm[3] += __expf(dd); }
        }
    }

    #pragma unroll
    for (int rr = 0; rr < 4; rr++) {
        float m = mx[rr], s = sm[rr];
        #pragma unroll
        for (int off = 16; off; off >>= 1) {
            const float om = __shfl_xor_sync(0xffffffffu, m, off);
            const float os = __shfl_xor_sync(0xffffffffu, s, off);
            const float nm = fmaxf(m, om);
            s = s * __expf(m - nm) + os * __expf(om - nm);
            m = nm;
        }
        if (lane == 0) { s_mx[rb + rr] = m; s_inv[rb + rr] = 1.f / s; }
    }
    __syncthreads();
    float fm[4], fi[4];
    #pragma unroll
    for (int rr = 0; rr < 4; rr++) { fm[rr] = s_mx[rb + rr]; fi[rr] = s_inv[rb + rr]; }

    for (int m0 = 0; m0 < NPIX; m0 += 256) {
        __syncthreads();
        #pragma unroll
        for (int r = 0; r < 4; r++) {
            const int lin = tid + 256 * r;
            const int d = lin >> 6, mm4 = (lin & 63) << 2;
            *(float4*)&ks[d][mm4] = *(const float4*)&kb[(size_t)d * NPIX + m0 + mm4];
        }
        __syncthreads();
        #pragma unroll
        for (int it = 0; it < 8; it++) {
            const int mm = lane + it * 32;
            float e0 = 0.f, e1 = 0.f, e2 = 0.f, e3 = 0.f;
            #pragma unroll
            for (int d = 0; d < 16; d++) {
                const float kv = ks[d][mm];
                e0 = fmaf(qr[0][d], kv, e0);
                e1 = fmaf(qr[1][d], kv, e1);
                e2 = fmaf(qr[2][d], kv, e2);
                e3 = fmaf(qr[3][d], kv, e3);
            }
            const float p0 = __expf(e0 - fm[0]) * fi[0];
            const float p1 = __expf(e1 - fm[1]) * fi[1];
            const float p2 = __expf(e2 - fm[2]) * fi[2];
            const float p3 = __expf(e3 - fm[3]) * fi[3];
            const size_t i0 = (size_t)(n0 + rb + 0) * NPIX + m0 + mm;
            const size_t i1 = (size_t)(n0 + rb + 1) * NPIX + m0 + mm;
            const size_t i2 = (size_t)(n0 + rb + 2) * NPIX + m0 + mm;
            const size_t i3 = (size_t)(n0 + rb + 3) * NPIX + m0 + mm;
            attb[i0] = p0; attb[i1] = p1; attb[i2] = p2; attb[i3] = p3;
            atth[i0] = __float2half_rn(p0); atth[i1] = __float2half_rn(p1);
            atth[i2] = __float2half_rn(p2); atth[i3] = __float2half_rn(p3);
        }
    }
}

// ===========================================================================
// Kernel 4: out-bmm via fp16 HMMA m16n8k16 + ldmatrix.
//   Block 128(c) x 128(n), 8 warps (4x2) of 32x64 tiles, 256 threads,
//   64 KB smem -> 2 CTAs/SM so independent CTAs overlap LDSM/MMA phases.
//   BK=32 fp16, 4-stage cp.async ring; 16B-chunk swizzle j ^= (row>>1)&3.
// ===========================================================================
#define HBM_ 128
#define HBN_ 128
#define HBK_ 32
#define H_A_BYTES (HBM_ * 64)                    // 8192
#define H_STAGE   ((HBM_ + HBN_) * 64)           // 16384
#define HNSTAGE   4
#define HSMEM     (HNSTAGE * H_STAGE)            // 65536

__global__ __launch_bounds__(256, 2) void out_gemm_h(
    const float* __restrict__ x1, const float* __restrict__ x2,
    float* __restrict__ out)
{
    extern __shared__ char smraw[];
    const uint32_t smb = smem_u32(smraw);

    const int tid  = threadIdx.x;
    const int wid  = tid >> 5;     // 0..7
    const int lane = tid & 31;
    const int grp  = lane >> 2;
    const int tig  = lane & 3;
    const int wm   = wid >> 1;     // 0..3 -> m offset 32*wm
    const int wn   = wid & 1;      // 0..1 -> n offset 64*wn

    const int which = blockIdx.z & 1;
    const int b     = blockIdx.z >> 1;
    const int n0    = blockIdx.x * HBN_;
    const int c0    = blockIdx.y * HBM_;

    const __half* __restrict__ Vb = g_v_h[which] + (size_t)b * CH * NPIX;
    const __half* __restrict__ Ah = g_att_h + (size_t)b * NPIX * NPIX;

    // ---- producer mapping (swizzled 16B chunks), 256 threads ----
    // A: 128 rows x 4 chunks = 512 -> 2 per thread
    const int a_row = tid >> 1;
    const int a_j0  = (tid & 1) * 2;
    const int a_sw  = (a_row >> 1) & 3;
    uint32_t aDst[2];
    #pragma unroll
    for (int i = 0; i < 2; i++)
        aDst[i] = smb + (uint32_t)(a_row * 64 + (((a_j0 + i) ^ a_sw) * 16));
    const __half* aSrc = Vb + (size_t)(c0 + a_row) * NPIX + a_j0 * 8;
    // B: 128 rows x 4 chunks = 512 -> 2 per thread
    const int b_row = tid >> 1;
    const int b_j0  = (tid & 1) * 2;
    const int b_sw  = (b_row >> 1) & 3;
    uint32_t bDst[2];
    #pragma unroll
    for (int i = 0; i < 2; i++)
        bDst[i] = smb + (uint32_t)(H_A_BYTES + b_row * 64 + (((b_j0 + i) ^ b_sw) * 16));
    const __half* bSrc = Ah + (size_t)(n0 + b_row) * NPIX + b_j0 * 8;

    // ---- ldmatrix lane constants ----
    const int radd = lane & 15;
    const int jA   = lane >> 4;
    const int lsw  = (radd >> 1) & 3;
    const uint32_t rowOff = (uint32_t)radd * 64;
    uint32_t cswk[2];
    cswk[0] = (uint32_t)(((0 + jA) ^ lsw) * 16);
    cswk[1] = (uint32_t)(((2 + jA) ^ lsw) * 16);

    float acc[2][8][4];
    #pragma unroll
    for (int mt = 0; mt < 2; mt++)
        #pragma unroll
        for (int nt = 0; nt < 8; nt++)
            #pragma unroll
            for (int q = 0; q < 4; q++) acc[mt][nt][q] = 0.f;

    const int KT = NPIX / HBK_;   // 128

    // prologue: stages 0..2
    #pragma unroll
    for (int s = 0; s < HNSTAGE - 1; s++) {
        const uint32_t so = (uint32_t)(s * H_STAGE);
        const int kc = s * HBK_;
        #pragma unroll
        for (int i = 0; i < 2; i++) CP_ASYNC16(aDst[i] + so, aSrc + kc + i * 8);
        #pragma unroll
        for (int i = 0; i < 2; i++) CP_ASYNC16(bDst[i] + so, bSrc + kc + i * 8);
        CP_COMMIT();
    }

    const uint32_t aWarp = smb + (uint32_t)(wm * 32) * 64 + rowOff;
    const uint32_t bWarp = smb + H_A_BYTES + (uint32_t)(wn * 64) * 64 + rowOff;

    for (int kt = 0; kt < KT; kt++) {
        CP_WAIT2();
        __syncthreads();

        const int nk = kt + HNSTAGE - 1;
        if (nk < KT) {
            const uint32_t so = (uint32_t)((nk & (HNSTAGE - 1)) * H_STAGE);
            const int kc = nk * HBK_;
            #pragma unroll
            for (int i = 0; i < 2; i++) CP_ASYNC16(aDst[i] + so, aSrc + kc + i * 8);
            #pragma unroll
            for (int i = 0; i < 2; i++) CP_ASYNC16(bDst[i] + so, bSrc + kc + i * 8);
        }
        CP_COMMIT();

        const uint32_t so = (uint32_t)((kt & (HNSTAGE - 1)) * H_STAGE);
        const uint32_t aB = aWarp + so;
        const uint32_t bB = bWarp + so;

        #pragma unroll
        for (int ksp = 0; ksp < 2; ksp++) {
            uint32_t af[2][4];
            #pragma unroll
            for (int mt = 0; mt < 2; mt++)
                LDSM_X4(af[mt][0], af[mt][1], af[mt][2], af[mt][3],
                        aB + (uint32_t)(mt * 1024) + cswk[ksp]);
            uint32_t bf[8][2];
            #pragma unroll
            for (int ntp = 0; ntp < 4; ntp++) {
                uint32_t q0, q1, q2, q3;
                LDSM_X4(q0, q1, q2, q3, bB + (uint32_t)(ntp * 1024) + cswk[ksp]);
                bf[2 * ntp    ][0] = q0; bf[2 * ntp    ][1] = q2;
                bf[2 * ntp + 1][0] = q1; bf[2 * ntp + 1][1] = q3;
            }
            #pragma unroll
            for (int mt = 0; mt < 2; mt++)
                #pragma unroll
                for (int nt = 0; nt < 8; nt++)
                    mma_f16(acc[mt][nt], af[mt], bf[nt]);
        }
        __syncthreads();
    }
    CP_WAIT0();

    // ---- epilogue: + residual x (fp32), store ----
    const float* __restrict__ Xb = (which ? x2 : x1) + (size_t)b * CH * NPIX;
    float* __restrict__ Ob = out + (size_t)which * BATCH * CH * NPIX + (size_t)b * CH * NPIX;

    #pragma unroll
    for (int mt = 0; mt < 2; mt++) {
        const int row0 = c0 + wm * 32 + mt * 16 + grp;
        const size_t r0b = (size_t)row0 * NPIX;
        const size_t r1b = (size_t)(row0 + 8) * NPIX;
        #pragma unroll
        for (int nt = 0; nt < 8; nt++) {
            const int col = n0 + wn * 64 + nt * 8 + tig * 2;
            const float2 x0 = *(const float2*)&Xb[r0b + col];
            const float2 x1v = *(const float2*)&Xb[r1b + col];
            float2 o0, o1;
            o0.x = acc[mt][nt][0] + x0.x;  o0.y = acc[mt][nt][1] + x0.y;
            o1.x = acc[mt][nt][2] + x1v.x; o1.y = acc[mt][nt][3] + x1v.y;
            *(float2*)&Ob[r0b + col] = o0;
            *(float2*)&Ob[r1b + col] = o1;
        }
    }
}

// ===========================================================================
// launch
// ===========================================================================
extern "C" void kernel_launch(void* const* d_in, const int* in_sizes, int n_in,
                              void* d_out, int out_size)
{
    (void)in_sizes; (void)n_in; (void)out_size;
    const float* x1  = (const float*)d_in[0];
    const float* x2  = (const float*)d_in[1];
    const float* Wq  = (const float*)d_in[2];
    const float* bq  = (const float*)d_in[3];
    const float* Wk  = (const float*)d_in[4];
    const float* bk  = (const float*)d_in[5];
    const float* Wv1 = (const float*)d_in[6];
    const float* bv1 = (const float*)d_in[7];
    const float* Wv2 = (const float*)d_in[8];
    const float* bv2 = (const float*)d_in[9];

    float* out = (float*)d_out;
    float* att = out + (size_t)2 * BATCH * CH * NPIX;

    cudaFuncSetAttribute(out_gemm_h, cudaFuncAttributeMaxDynamicSharedMemorySize, HSMEM);

    qk_kernel<<<dim3(NPIX / 32, BATCH), 256>>>(x1, x2, Wq, bq, Wk, bk);
    v_gemm_kernel<<<dim3(NPIX / BN, CH / BM, BATCH * 2), 256>>>(x1, x2, Wv1, bv1, Wv2, bv2);
    attn_kernel<<<dim3(NPIX / 32, BATCH), 256>>>(att);
    out_gemm_h<<<dim3(NPIX / HBN_, CH / HBM_, BATCH * 2), 256, HSMEM>>>(x1, x2, out);
}

// round 15
// speedup vs baseline: 1.1987x; 1.1221x over previous
#include <cuda_runtime.h>
#include <cuda_fp16.h>
#include <cstdint>

// ---------------------------------------------------------------------------
// SpatialCrossAttention — fp16 HMMA out-bmm + unnormalized-p attention
//   B=8, C=256, N=4096, DQK=16
//   out layout: [out1 | out2 | attention]
//   att pipeline: p = exp(e)/16 stored fp16 (unnormalized), inv = 1/sum(p);
//   fp32 att = p*inv (memory-only kernel); out-bmm normalizes in epilogue.
// ---------------------------------------------------------------------------

#define BATCH 8
#define CH    256
#define NPIX  4096
#define DQK   16
#define TWO_C 512

// SIMT GEMM tiling (v projection)
#define BM 128
#define BN 128
#define TK 16
#define PAD 4

// ---- device scratch ----
__device__ float  g_q[BATCH * DQK * NPIX];
__device__ float  g_k[BATCH * DQK * NPIX];
__device__ float  g_inv[BATCH * NPIX];
__device__ __half g_v_h[2][BATCH * CH * NPIX];            // 32 MB
__device__ __half g_att_h[(size_t)BATCH * NPIX * NPIX];   // 256 MB (unnormalized p)

// ===========================================================================
// helpers
// ===========================================================================
__device__ __forceinline__ uint32_t smem_u32(const void* p) {
    uint32_t a;
    asm("{ .reg .u64 t; cvta.to.shared.u64 t, %1; cvt.u32.u64 %0, t; }" : "=r"(a) : "l"(p));
    return a;
}

__device__ __forceinline__ uint32_t pack_h2(float lo, float hi) {
    __half2 h = __floats2half2_rn(lo, hi);
    return *(uint32_t*)&h;
}

#define CP_ASYNC16(dst, src) \
    asm volatile("cp.async.cg.shared.global [%0], [%1], 16;" :: "r"(dst), "l"(src) : "memory")
#define CP_COMMIT() asm volatile("cp.async.commit_group;" ::: "memory")
#define CP_WAIT2()  asm volatile("cp.async.wait_group 2;" ::: "memory")
#define CP_WAIT0()  asm volatile("cp.async.wait_group 0;" ::: "memory")

#define LDSM_X4(r0, r1, r2, r3, addr) \
    asm volatile("ldmatrix.sync.aligned.m8n8.x4.shared.b16 {%0,%1,%2,%3}, [%4];" \
                 : "=r"(r0), "=r"(r1), "=r"(r2), "=r"(r3) : "r"(addr))

__device__ __forceinline__ void mma_f16(float* c, const uint32_t* a, const uint32_t* b) {
    asm volatile(
        "mma.sync.aligned.m16n8k16.row.col.f32.f16.f16.f32 "
        "{%0,%1,%2,%3}, {%4,%5,%6,%7}, {%8,%9}, {%0,%1,%2,%3};"
        : "+f"(c[0]), "+f"(c[1]), "+f"(c[2]), "+f"(c[3])
        : "r"(a[0]), "r"(a[1]), "r"(a[2]), "r"(a[3]), "r"(b[0]), "r"(b[1]));
}

// ===========================================================================
// Kernel 1: q/k projection (unchanged)
// ===========================================================================
__global__ __launch_bounds__(256) void qk_kernel(
    const float* __restrict__ x1, const float* __restrict__ x2,
    const float* __restrict__ Wq, const float* __restrict__ bq,
    const float* __restrict__ Wk, const float* __restrict__ bk)
{
    __shared__ float xs[64][33];
    __shared__ float wqs[16][64];
    __shared__ float wks[16][64];

    const int n0  = blockIdx.x * 32;
    const int b   = blockIdx.y;
    const int tid = threadIdx.x;
    const int nl  = tid & 31;
    const int dg  = tid >> 5;

    float aq0 = 0.f, aq1 = 0.f, ak0 = 0.f, ak1 = 0.f;

    for (int c0 = 0; c0 < TWO_C; c0 += 64) {
        for (int r = dg; r < 64; r += 8) {
            const int c = c0 + r;
            const float* src = (c < CH) ? x1 : x2;
            xs[r][nl] = src[((size_t)b * CH + (c & (CH - 1))) * NPIX + n0 + nl];
        }
        for (int i = tid; i < 16 * 64; i += 256) {
            const int d = i >> 6, cc = i & 63;
            wqs[d][cc] = Wq[d * TWO_C + c0 + cc];
            wks[d][cc] = Wk[d * TWO_C + c0 + cc];
        }
        __syncthreads();
        #pragma unroll
        for (int cc = 0; cc < 64; cc++) {
            const float xv = xs[cc][nl];
            aq0 = fmaf(wqs[dg    ][cc], xv, aq0);
            aq1 = fmaf(wqs[dg + 8][cc], xv, aq1);
            ak0 = fmaf(wks[dg    ][cc], xv, ak0);
            ak1 = fmaf(wks[dg + 8][cc], xv, ak1);
        }
        __syncthreads();
    }

    const size_t base = (size_t)b * DQK * NPIX + n0 + nl;
    g_q[base + (size_t)(dg    ) * NPIX] = aq0 + bq[dg];
    g_q[base + (size_t)(dg + 8) * NPIX] = aq1 + bq[dg + 8];
    g_k[base + (size_t)(dg    ) * NPIX] = ak0 + bk[dg];
    g_k[base + (size_t)(dg + 8) * NPIX] = ak1 + bk[dg + 8];
}

// ===========================================================================
// Kernel 2: v projection GEMM (unchanged)
// ===========================================================================
__global__ __launch_bounds__(256, 2) void v_gemm_kernel(
    const float* __restrict__ x1, const float* __restrict__ x2,
    const float* __restrict__ Wv1, const float* __restrict__ bv1,
    const float* __restrict__ Wv2, const float* __restrict__ bv2)
{
    __shared__ float As[2][TK][BM + PAD];
    __shared__ float Bs[2][TK][BN + PAD];

    const int which = blockIdx.z & 1;
    const int b     = blockIdx.z >> 1;
    const float* __restrict__ Wv = which ? Wv2 : Wv1;
    const float* __restrict__ bv = which ? bv2 : bv1;
    const float* __restrict__ Xb = (which ? x2 : x1) + (size_t)b * CH * NPIX;
    __half* __restrict__ V       = g_v_h[which] + (size_t)b * CH * NPIX;

    const int n0  = blockIdx.x * BN;
    const int o0  = blockIdx.y * BM;
    const int tid = threadIdx.x;
    const int tx  = tid & 15, ty = tid >> 4;

    const int ar  = tid >> 2;
    const int ak  = (tid & 3) << 2;
    const int bkr = tid >> 5;
    const int bj  = (tid & 31) << 2;

    float acc[8][8];
    #pragma unroll
    for (int r = 0; r < 8; r++)
        #pragma unroll
        for (int s = 0; s < 8; s++) acc[r][s] = 0.f;

    const int KT = CH / TK;
    float4 a0n, a1n, b0n, b1n;

    {
        const float* ap = Wv + (o0 + ar) * CH + ak;
        a0n = *(const float4*)ap;
        a1n = *(const float4*)(ap + 64 * CH);
        const float* bp = Xb + (size_t)bkr * NPIX + n0 + bj;
        b0n = *(const float4*)bp;
        b1n = *(const float4*)(bp + (size_t)8 * NPIX);
        As[0][ak + 0][ar] = a0n.x; As[0][ak + 1][ar] = a0n.y;
        As[0][ak + 2][ar] = a0n.z; As[0][ak + 3][ar] = a0n.w;
        As[0][ak + 0][ar + 64] = a1n.x; As[0][ak + 1][ar + 64] = a1n.y;
        As[0][ak + 2][ar + 64] = a1n.z; As[0][ak + 3][ar + 64] = a1n.w;
        *(float4*)&Bs[0][bkr    ][bj] = b0n;
        *(float4*)&Bs[0][bkr + 8][bj] = b1n;
    }
    __syncthreads();

    for (int kt = 0; kt < KT; kt++) {
        const int cur = kt & 1;
        const bool pf = (kt + 1 < KT);
        if (pf) {
            const int kc = (kt + 1) * TK;
            const float* ap = Wv + (o0 + ar) * CH + kc + ak;
            a0n = *(const float4*)ap;
            a1n = *(const float4*)(ap + 64 * CH);
            const float* bp = Xb + (size_t)(kc + bkr) * NPIX + n0 + bj;
            b0n = *(const float4*)bp;
            b1n = *(const float4*)(bp + (size_t)8 * NPIX);
        }
        #pragma unroll
        for (int k = 0; k < TK; k++) {
            const float4 a0 = *(const float4*)&As[cur][k][ty * 4];
            const float4 a1 = *(const float4*)&As[cur][k][64 + ty * 4];
            const float4 b0 = *(const float4*)&Bs[cur][k][tx * 4];
            const float4 b1 = *(const float4*)&Bs[cur][k][64 + tx * 4];
            const float av[8] = {a0.x, a0.y, a0.z, a0.w, a1.x, a1.y, a1.z, a1.w};
            const float bw[8] = {b0.x, b0.y, b0.z, b0.w, b1.x, b1.y, b1.z, b1.w};
            #pragma unroll
            for (int r = 0; r < 8; r++)
                #pragma unroll
                for (int s = 0; s < 8; s++)
                    acc[r][s] = fmaf(av[r], bw[s], acc[r][s]);
        }
        if (pf) {
            const int nb = cur ^ 1;
            As[nb][ak + 0][ar] = a0n.x; As[nb][ak + 1][ar] = a0n.y;
            As[nb][ak + 2][ar] = a0n.z; As[nb][ak + 3][ar] = a0n.w;
            As[nb][ak + 0][ar + 64] = a1n.x; As[nb][ak + 1][ar + 64] = a1n.y;
            As[nb][ak + 2][ar + 64] = a1n.z; As[nb][ak + 3][ar + 64] = a1n.w;
            *(float4*)&Bs[nb][bkr    ][bj] = b0n;
            *(float4*)&Bs[nb][bkr + 8][bj] = b1n;
        }
        __syncthreads();
    }

    #pragma unroll
    for (int rg = 0; rg < 2; rg++)
        #pragma unroll
        for (int rr = 0; rr < 4; rr++) {
            const int r = rg * 4 + rr;
            const int o = o0 + rg * 64 + ty * 4 + rr;
            const float bias = __ldg(&bv[o]);
            __half* dst = V + (size_t)o * NPIX + n0;
            uint2 h0, h1;
            h0.x = pack_h2(acc[r][0] + bias, acc[r][1] + bias);
            h0.y = pack_h2(acc[r][2] + bias, acc[r][3] + bias);
            h1.x = pack_h2(acc[r][4] + bias, acc[r][5] + bias);
            h1.y = pack_h2(acc[r][6] + bias, acc[r][7] + bias);
            *(uint2*)(dst + tx * 4)      = h0;
            *(uint2*)(dst + 64 + tx * 4) = h1;
        }
}

// ===========================================================================
// Kernel 3: single-pass energy -> p = exp(e)/16 (fp16, unnormalized) + row inv.
//   32 query rows/block; warp w owns rows 4w..4w+3. One k-stream.
// ===========================================================================
__global__ __launch_bounds__(256) void attn_p_kernel()
{
    __shared__ float ks[16][256];
    __shared__ float qs[16][32];

    const int n0   = blockIdx.x * 32;
    const int b    = blockIdx.y;
    const int tid  = threadIdx.x;
    const int lane = tid & 31;
    const int w    = tid >> 5;
    const int rb   = w * 4;

    const float* __restrict__ qb = g_q + (size_t)b * DQK * NPIX;
    const float* __restrict__ kb = g_k + (size_t)b * DQK * NPIX;
    __half* __restrict__ atth    = g_att_h + (size_t)b * NPIX * NPIX;

    for (int i = tid; i < 512; i += 256) {
        const int d = i >> 5, nl = i & 31;
        qs[d][nl] = qb[(size_t)d * NPIX + n0 + nl];
    }
    __syncthreads();
    float qr[4][16];
    #pragma unroll
    for (int rr = 0; rr < 4; rr++)
        #pragma unroll
        for (int d = 0; d < 16; d++)
            qr[rr][d] = qs[d][rb + rr];

    float sm[4] = {0.f, 0.f, 0.f, 0.f};

    for (int m0 = 0; m0 < NPIX; m0 += 256) {
        __syncthreads();
        #pragma unroll
        for (int r = 0; r < 4; r++) {
            const int lin = tid + 256 * r;
            const int d = lin >> 6, mm4 = (lin & 63) << 2;
            *(float4*)&ks[d][mm4] = *(const float4*)&kb[(size_t)d * NPIX + m0 + mm4];
        }
        __syncthreads();
        #pragma unroll
        for (int it = 0; it < 8; it++) {
            const int mm = lane + it * 32;
            float e0 = 0.f, e1 = 0.f, e2 = 0.f, e3 = 0.f;
            #pragma unroll
            for (int d = 0; d < 16; d++) {
                const float kv = ks[d][mm];
                e0 = fmaf(qr[0][d], kv, e0);
                e1 = fmaf(qr[1][d], kv, e1);
                e2 = fmaf(qr[2][d], kv, e2);
                e3 = fmaf(qr[3][d], kv, e3);
            }
            // scale by 1/16: fp16-overflow insurance (p <= ~70 for e <= ~7)
            const float p0 = __expf(e0) * 0.0625f;
            const float p1 = __expf(e1) * 0.0625f;
            const float p2 = __expf(e2) * 0.0625f;
            const float p3 = __expf(e3) * 0.0625f;
            sm[0] += p0; sm[1] += p1; sm[2] += p2; sm[3] += p3;
            atth[(size_t)(n0 + rb + 0) * NPIX + m0 + mm] = __float2half_rn(p0);
            atth[(size_t)(n0 + rb + 1) * NPIX + m0 + mm] = __float2half_rn(p1);
            atth[(size_t)(n0 + rb + 2) * NPIX + m0 + mm] = __float2half_rn(p2);
            atth[(size_t)(n0 + rb + 3) * NPIX + m0 + mm] = __float2half_rn(p3);
        }
    }

    #pragma unroll
    for (int rr = 0; rr < 4; rr++) {
        float s = sm[rr];
        #pragma unroll
        for (int off = 16; off; off >>= 1)
            s += __shfl_xor_sync(0xffffffffu, s, off);
        if (lane == 0) g_inv[b * NPIX + n0 + rb + rr] = 1.f / s;
    }
}

// ===========================================================================
// Kernel 3b: att_norm — fp32 attention = fp16(p) * inv[row]. Memory-only.
//   grid (2, NPIX, B), 256 threads; thread handles 8 contiguous elements.
// ===========================================================================
__global__ __launch_bounds__(256) void att_norm_kernel(float* __restrict__ att)
{
    const int b = blockIdx.z;
    const int n = blockIdx.y;
    const int m0 = blockIdx.x * 2048 + threadIdx.x * 8;
    const float inv = g_inv[b * NPIX + n];
    const __half* __restrict__ src = g_att_h + ((size_t)b * NPIX + n) * NPIX + m0;
    float* __restrict__ dst = att + ((size_t)b * NPIX + n) * NPIX + m0;

    const uint4 raw = *(const uint4*)src;
    const __half2* h2 = (const __half2*)&raw;
    float4 o0, o1;
    float2 t;
    t = __half22float2(h2[0]); o0.x = t.x * inv; o0.y = t.y * inv;
    t = __half22float2(h2[1]); o0.z = t.x * inv; o0.w = t.y * inv;
    t = __half22float2(h2[2]); o1.x = t.x * inv; o1.y = t.y * inv;
    t = __half22float2(h2[3]); o1.z = t.x * inv; o1.w = t.y * inv;
    *(float4*)dst       = o0;
    *(float4*)(dst + 4) = o1;
}

// ===========================================================================
// Kernel 4: out-bmm via fp16 HMMA m16n8k16 + ldmatrix (128x128, 2 CTAs/SM).
//   B operand = unnormalized p; epilogue: out = D*inv[n] + x.
// ===========================================================================
#define HBM_ 128
#define HBN_ 128
#define HBK_ 32
#define H_A_BYTES (HBM_ * 64)                    // 8192
#define H_STAGE   ((HBM_ + HBN_) * 64)           // 16384
#define HNSTAGE   4
#define HSMEM     (HNSTAGE * H_STAGE)            // 65536

__global__ __launch_bounds__(256, 2) void out_gemm_h(
    const float* __restrict__ x1, const float* __restrict__ x2,
    float* __restrict__ out)
{
    extern __shared__ char smraw[];
    const uint32_t smb = smem_u32(smraw);

    const int tid  = threadIdx.x;
    const int wid  = tid >> 5;     // 0..7
    const int lane = tid & 31;
    const int grp  = lane >> 2;
    const int tig  = lane & 3;
    const int wm   = wid >> 1;     // 0..3 -> m offset 32*wm
    const int wn   = wid & 1;      // 0..1 -> n offset 64*wn

    const int which = blockIdx.z & 1;
    const int b     = blockIdx.z >> 1;
    const int n0    = blockIdx.x * HBN_;
    const int c0    = blockIdx.y * HBM_;

    const __half* __restrict__ Vb = g_v_h[which] + (size_t)b * CH * NPIX;
    const __half* __restrict__ Ah = g_att_h + (size_t)b * NPIX * NPIX;

    // ---- producer mapping (swizzled 16B chunks), 256 threads ----
    const int a_row = tid >> 1;
    const int a_j0  = (tid & 1) * 2;
    const int a_sw  = (a_row >> 1) & 3;
    uint32_t aDst[2];
    #pragma unroll
    for (int i = 0; i < 2; i++)
        aDst[i] = smb + (uint32_t)(a_row * 64 + (((a_j0 + i) ^ a_sw) * 16));
    const __half* aSrc = Vb + (size_t)(c0 + a_row) * NPIX + a_j0 * 8;
    const int b_row = tid >> 1;
    const int b_j0  = (tid & 1) * 2;
    const int b_sw  = (b_row >> 1) & 3;
    uint32_t bDst[2];
    #pragma unroll
    for (int i = 0; i < 2; i++)
        bDst[i] = smb + (uint32_t)(H_A_BYTES + b_row * 64 + (((b_j0 + i) ^ b_sw) * 16));
    const __half* bSrc = Ah + (size_t)(n0 + b_row) * NPIX + b_j0 * 8;

    // ---- ldmatrix lane constants ----
    const int radd = lane & 15;
    const int jA   = lane >> 4;
    const int lsw  = (radd >> 1) & 3;
    const uint32_t rowOff = (uint32_t)radd * 64;
    uint32_t cswk[2];
    cswk[0] = (uint32_t)(((0 + jA) ^ lsw) * 16);
    cswk[1] = (uint32_t)(((2 + jA) ^ lsw) * 16);

    float acc[2][8][4];
    #pragma unroll
    for (int mt = 0; mt < 2; mt++)
        #pragma unroll
        for (int nt = 0; nt < 8; nt++)
            #pragma unroll
            for (int q = 0; q < 4; q++) acc[mt][nt][q] = 0.f;

    const int KT = NPIX / HBK_;   // 128

    #pragma unroll
    for (int s = 0; s < HNSTAGE - 1; s++) {
        const uint32_t so = (uint32_t)(s * H_STAGE);
        const int kc = s * HBK_;
        #pragma unroll
        for (int i = 0; i < 2; i++) CP_ASYNC16(aDst[i] + so, aSrc + kc + i * 8);
        #pragma unroll
        for (int i = 0; i < 2; i++) CP_ASYNC16(bDst[i] + so, bSrc + kc + i * 8);
        CP_COMMIT();
    }

    const uint32_t aWarp = smb + (uint32_t)(wm * 32) * 64 + rowOff;
    const uint32_t bWarp = smb + H_A_BYTES + (uint32_t)(wn * 64) * 64 + rowOff;

    for (int kt = 0; kt < KT; kt++) {
        CP_WAIT2();
        __syncthreads();

        const int nk = kt + HNSTAGE - 1;
        if (nk < KT) {
            const uint32_t so = (uint32_t)((nk & (HNSTAGE - 1)) * H_STAGE);
            const int kc = nk * HBK_;
            #pragma unroll
            for (int i = 0; i < 2; i++) CP_ASYNC16(aDst[i] + so, aSrc + kc + i * 8);
            #pragma unroll
            for (int i = 0; i < 2; i++) CP_ASYNC16(bDst[i] + so, bSrc + kc + i * 8);
        }
        CP_COMMIT();

        const uint32_t so = (uint32_t)((kt & (HNSTAGE - 1)) * H_STAGE);
        const uint32_t aB = aWarp + so;
        const uint32_t bB = bWarp + so;

        #pragma unroll
        for (int ksp = 0; ksp < 2; ksp++) {
            uint32_t af[2][4];
            #pragma unroll
            for (int mt = 0; mt < 2; mt++)
                LDSM_X4(af[mt][0], af[mt][1], af[mt][2], af[mt][3],
                        aB + (uint32_t)(mt * 1024) + cswk[ksp]);
            uint32_t bf[8][2];
            #pragma unroll
            for (int ntp = 0; ntp < 4; ntp++) {
                uint32_t q0, q1, q2, q3;
                LDSM_X4(q0, q1, q2, q3, bB + (uint32_t)(ntp * 1024) + cswk[ksp]);
                bf[2 * ntp    ][0] = q0; bf[2 * ntp    ][1] = q2;
                bf[2 * ntp + 1][0] = q1; bf[2 * ntp + 1][1] = q3;
            }
            #pragma unroll
            for (int mt = 0; mt < 2; mt++)
                #pragma unroll
                for (int nt = 0; nt < 8; nt++)
                    mma_f16(acc[mt][nt], af[mt], bf[nt]);
        }
        __syncthreads();
    }
    CP_WAIT0();

    // ---- epilogue: D*inv[n] + x (fp32), store ----
    const float* __restrict__ Xb = (which ? x2 : x1) + (size_t)b * CH * NPIX;
    float* __restrict__ Ob = out + (size_t)which * BATCH * CH * NPIX + (size_t)b * CH * NPIX;
    const float* __restrict__ invb = g_inv + (size_t)b * NPIX;

    #pragma unroll
    for (int mt = 0; mt < 2; mt++) {
        const int row0 = c0 + wm * 32 + mt * 16 + grp;
        const size_t r0b = (size_t)row0 * NPIX;
        const size_t r1b = (size_t)(row0 + 8) * NPIX;
        #pragma unroll
        for (int nt = 0; nt < 8; nt++) {
            const int col = n0 + wn * 64 + nt * 8 + tig * 2;
            const float2 iv = *(const float2*)&invb[col];
            const float2 x0 = *(const float2*)&Xb[r0b + col];
            const float2 x1v = *(const float2*)&Xb[r1b + col];
            float2 o0, o1;
            o0.x = fmaf(acc[mt][nt][0], iv.x, x0.x);
            o0.y = fmaf(acc[mt][nt][1], iv.y, x0.y);
            o1.x = fmaf(acc[mt][nt][2], iv.x, x1v.x);
            o1.y = fmaf(acc[mt][nt][3], iv.y, x1v.y);
            *(float2*)&Ob[r0b + col] = o0;
            *(float2*)&Ob[r1b + col] = o1;
        }
    }
}

// ===========================================================================
// launch
// ===========================================================================
extern "C" void kernel_launch(void* const* d_in, const int* in_sizes, int n_in,
                              void* d_out, int out_size)
{
    (void)in_sizes; (void)n_in; (void)out_size;
    const float* x1  = (const float*)d_in[0];
    const float* x2  = (const float*)d_in[1];
    const float* Wq  = (const float*)d_in[2];
    const float* bq  = (const float*)d_in[3];
    const float* Wk  = (const float*)d_in[4];
    const float* bk  = (const float*)d_in[5];
    const float* Wv1 = (const float*)d_in[6];
    const float* bv1 = (const float*)d_in[7];
    const float* Wv2 = (const float*)d_in[8];
    const float* bv2 = (const float*)d_in[9];

    float* out = (float*)d_out;
    float* att = out + (size_t)2 * BATCH * CH * NPIX;

    cudaFuncSetAttribute(out_gemm_h, cudaFuncAttributeMaxDynamicSharedMemorySize, HSMEM);

    qk_kernel<<<dim3(NPIX / 32, BATCH), 256>>>(x1, x2, Wq, bq, Wk, bk);
    v_gemm_kernel<<<dim3(NPIX / BN, CH / BM, BATCH * 2), 256>>>(x1, x2, Wv1, bv1, Wv2, bv2);
    attn_p_kernel<<<dim3(NPIX / 32, BATCH), 256>>>();
    att_norm_kernel<<<dim3(2, NPIX, BATCH), 256>>>(att);
    out_gemm_h<<<dim3(NPIX / HBN_, CH / HBM_, BATCH * 2), 256, HSMEM>>>(x1, x2, out);
}

// round 16
// speedup vs baseline: 1.3320x; 1.1112x over previous
#include <cuda_runtime.h>
#include <cuda_fp16.h>
#include <cstdint>

// ---------------------------------------------------------------------------
// SpatialCrossAttention — all-HMMA GEMMs + unnormalized-p attention
//   B=8, C=256, N=4096, DQK=16
//   out layout: [out1 | out2 | attention]
// ---------------------------------------------------------------------------

#define BATCH 8
#define CH    256
#define NPIX  4096
#define DQK   16
#define TWO_C 512

// ---- device scratch ----
__device__ float  g_q[BATCH * DQK * NPIX];
__device__ float  g_k[BATCH * DQK * NPIX];
__device__ float  g_inv[BATCH * NPIX];
__device__ __half g_w_h[2][CH * CH];                      // fp16 Wv
__device__ __half g_xT_h[2][BATCH * NPIX * CH];           // fp16 x, [n][c] layout
__device__ __half g_v_h[2][BATCH * CH * NPIX];            // 32 MB
__device__ __half g_att_h[(size_t)BATCH * NPIX * NPIX];   // 256 MB (unnormalized p)

// ===========================================================================
// helpers
// ===========================================================================
__device__ __forceinline__ uint32_t smem_u32(const void* p) {
    uint32_t a;
    asm("{ .reg .u64 t; cvta.to.shared.u64 t, %1; cvt.u32.u64 %0, t; }" : "=r"(a) : "l"(p));
    return a;
}

#define CP_ASYNC16(dst, src) \
    asm volatile("cp.async.cg.shared.global [%0], [%1], 16;" :: "r"(dst), "l"(src) : "memory")
#define CP_COMMIT() asm volatile("cp.async.commit_group;" ::: "memory")
#define CP_WAIT2()  asm volatile("cp.async.wait_group 2;" ::: "memory")
#define CP_WAIT0()  asm volatile("cp.async.wait_group 0;" ::: "memory")

#define LDSM_X4(r0, r1, r2, r3, addr) \
    asm volatile("ldmatrix.sync.aligned.m8n8.x4.shared.b16 {%0,%1,%2,%3}, [%4];" \
                 : "=r"(r0), "=r"(r1), "=r"(r2), "=r"(r3) : "r"(addr))

__device__ __forceinline__ void mma_f16(float* c, const uint32_t* a, const uint32_t* b) {
    asm volatile(
        "mma.sync.aligned.m16n8k16.row.col.f32.f16.f16.f32 "
        "{%0,%1,%2,%3}, {%4,%5,%6,%7}, {%8,%9}, {%0,%1,%2,%3};"
        : "+f"(c[0]), "+f"(c[1]), "+f"(c[2]), "+f"(c[3])
        : "r"(a[0]), "r"(a[1]), "r"(a[2]), "r"(a[3]), "r"(b[0]), "r"(b[1]));
}

// ===========================================================================
// Kernel 0a: Wv -> fp16
// ===========================================================================
__global__ __launch_bounds__(256) void wconv_kernel(
    const float* __restrict__ Wv1, const float* __restrict__ Wv2)
{
    const int which = blockIdx.y;
    const float* __restrict__ src = which ? Wv2 : Wv1;
    __half* __restrict__ dst = g_w_h[which];
    const int i = (blockIdx.x * 256 + threadIdx.x) * 4;
    const float4 v = *(const float4*)&src[i];
    __half2 h0 = __floats2half2_rn(v.x, v.y);
    __half2 h1 = __floats2half2_rn(v.z, v.w);
    uint2 o; o.x = *(uint32_t*)&h0; o.y = *(uint32_t*)&h1;
    *(uint2*)&dst[i] = o;
}

// ===========================================================================
// Kernel 0b: x -> fp16 transposed [n][c]  (32x32 smem tiles)
// grid (NPIX/32, CH/32, 16), z = b*2 + which
// ===========================================================================
__global__ __launch_bounds__(256) void xtrans_kernel(
    const float* __restrict__ x1, const float* __restrict__ x2)
{
    __shared__ float t[32][33];
    const int which = blockIdx.z & 1;
    const int b     = blockIdx.z >> 1;
    const int n0    = blockIdx.x * 32;
    const int c0    = blockIdx.y * 32;
    const float* __restrict__ Xb = (which ? x2 : x1) + (size_t)b * CH * NPIX;
    __half* __restrict__ XT = g_xT_h[which] + (size_t)b * NPIX * CH;

    const int tid  = threadIdx.x;
    const int lane = tid & 31;
    const int rg   = tid >> 5;
    #pragma unroll
    for (int i = 0; i < 4; i++) {
        const int c = rg + i * 8;
        t[c][lane] = Xb[(size_t)(c0 + c) * NPIX + n0 + lane];
    }
    __syncthreads();
    const int n  = tid >> 3;
    const int cc = (tid & 7) * 4;
    __half2 h0 = __floats2half2_rn(t[cc + 0][n], t[cc + 1][n]);
    __half2 h1 = __floats2half2_rn(t[cc + 2][n], t[cc + 3][n]);
    uint2 o; o.x = *(uint32_t*)&h0; o.y = *(uint32_t*)&h1;
    *(uint2*)&XT[(size_t)(n0 + n) * CH + c0 + cc] = o;
}

// ===========================================================================
// Kernel 1: q/k projection (unchanged)
// ===========================================================================
__global__ __launch_bounds__(256) void qk_kernel(
    const float* __restrict__ x1, const float* __restrict__ x2,
    const float* __restrict__ Wq, const float* __restrict__ bq,
    const float* __restrict__ Wk, const float* __restrict__ bk)
{
    __shared__ float xs[64][33];
    __shared__ float wqs[16][64];
    __shared__ float wks[16][64];

    const int n0  = blockIdx.x * 32;
    const int b   = blockIdx.y;
    const int tid = threadIdx.x;
    const int nl  = tid & 31;
    const int dg  = tid >> 5;

    float aq0 = 0.f, aq1 = 0.f, ak0 = 0.f, ak1 = 0.f;

    for (int c0 = 0; c0 < TWO_C; c0 += 64) {
        for (int r = dg; r < 64; r += 8) {
            const int c = c0 + r;
            const float* src = (c < CH) ? x1 : x2;
            xs[r][nl] = src[((size_t)b * CH + (c & (CH - 1))) * NPIX + n0 + nl];
        }
        for (int i = tid; i < 16 * 64; i += 256) {
            const int d = i >> 6, cc = i & 63;
            wqs[d][cc] = Wq[d * TWO_C + c0 + cc];
            wks[d][cc] = Wk[d * TWO_C + c0 + cc];
        }
        __syncthreads();
        #pragma unroll
        for (int cc = 0; cc < 64; cc++) {
            const float xv = xs[cc][nl];
            aq0 = fmaf(wqs[dg    ][cc], xv, aq0);
            aq1 = fmaf(wqs[dg + 8][cc], xv, aq1);
            ak0 = fmaf(wks[dg    ][cc], xv, ak0);
            ak1 = fmaf(wks[dg + 8][cc], xv, ak1);
        }
        __syncthreads();
    }

    const size_t base = (size_t)b * DQK * NPIX + n0 + nl;
    g_q[base + (size_t)(dg    ) * NPIX] = aq0 + bq[dg];
    g_q[base + (size_t)(dg + 8) * NPIX] = aq1 + bq[dg + 8];
    g_k[base + (size_t)(dg    ) * NPIX] = ak0 + bk[dg];
    g_k[base + (size_t)(dg + 8) * NPIX] = ak1 + bk[dg + 8];
}

// ===========================================================================
// Kernel 2: v projection via fp16 HMMA (out_gemm skeleton, K=256).
//   V[o, n] = sum_c Wh[o, c] * xT[n, c] + bv[o];  stores fp16 V [o][n].
//   Block 128(o) x 128(n), 8 warps (4x2), 2 CTAs/SM, BK=32, 4-stage ring.
// ===========================================================================
#define VK 256
#define V_A_BYTES (128 * 64)
#define V_STAGE   (256 * 64)
#define VNSTAGE   4
#define VSMEM     (VNSTAGE * V_STAGE)   // 65536

__global__ __launch_bounds__(256, 2) void v_gemm_h(
    const float* __restrict__ bv1, const float* __restrict__ bv2)
{
    extern __shared__ char smraw[];
    const uint32_t smb = smem_u32(smraw);

    const int tid  = threadIdx.x;
    const int wid  = tid >> 5;
    const int lane = tid & 31;
    const int grp  = lane >> 2;
    const int tig  = lane & 3;
    const int wm   = wid >> 1;     // 0..3
    const int wn   = wid & 1;      // 0..1

    const int which = blockIdx.z & 1;
    const int b     = blockIdx.z >> 1;
    const int n0    = blockIdx.x * 128;
    const int o0    = blockIdx.y * 128;

    const __half* __restrict__ Wh = g_w_h[which];
    const __half* __restrict__ XT = g_xT_h[which] + (size_t)b * NPIX * CH;
    const float* __restrict__ bv  = which ? bv2 : bv1;
    __half* __restrict__ V        = g_v_h[which] + (size_t)b * CH * NPIX;

    // producer mapping (identical swizzle to out_gemm; row strides = 256)
    const int a_row = tid >> 1;
    const int a_j0  = (tid & 1) * 2;
    const int a_sw  = (a_row >> 1) & 3;
    uint32_t aDst[2];
    #pragma unroll
    for (int i = 0; i < 2; i++)
        aDst[i] = smb + (uint32_t)(a_row * 64 + (((a_j0 + i) ^ a_sw) * 16));
    const __half* aSrc = Wh + (size_t)(o0 + a_row) * VK + a_j0 * 8;
    uint32_t bDst[2];
    #pragma unroll
    for (int i = 0; i < 2; i++)
        bDst[i] = smb + (uint32_t)(V_A_BYTES + a_row * 64 + (((a_j0 + i) ^ a_sw) * 16));
    const __half* bSrc = XT + (size_t)(n0 + a_row) * VK + a_j0 * 8;

    const int radd = lane & 15;
    const int jA   = lane >> 4;
    const int lsw  = (radd >> 1) & 3;
    const uint32_t rowOff = (uint32_t)radd * 64;
    uint32_t cswk[2];
    cswk[0] = (uint32_t)(((0 + jA) ^ lsw) * 16);
    cswk[1] = (uint32_t)(((2 + jA) ^ lsw) * 16);

    float acc[2][8][4];
    #pragma unroll
    for (int mt = 0; mt < 2; mt++)
        #pragma unroll
        for (int nt = 0; nt < 8; nt++)
            #pragma unroll
            for (int q = 0; q < 4; q++) acc[mt][nt][q] = 0.f;

    const int KT = VK / 32;   // 8

    #pragma unroll
    for (int s = 0; s < VNSTAGE - 1; s++) {
        const uint32_t so = (uint32_t)(s * V_STAGE);
        const int kc = s * 32;
        #pragma unroll
        for (int i = 0; i < 2; i++) CP_ASYNC16(aDst[i] + so, aSrc + kc + i * 8);
        #pragma unroll
        for (int i = 0; i < 2; i++) CP_ASYNC16(bDst[i] + so, bSrc + kc + i * 8);
        CP_COMMIT();
    }

    const uint32_t aWarp = smb + (uint32_t)(wm * 32) * 64 + rowOff;
    const uint32_t bWarp = smb + V_A_BYTES + (uint32_t)(wn * 64) * 64 + rowOff;

    for (int kt = 0; kt < KT; kt++) {
        CP_WAIT2();
        __syncthreads();

        const int nk = kt + VNSTAGE - 1;
        if (nk < KT) {
            const uint32_t so = (uint32_t)((nk & (VNSTAGE - 1)) * V_STAGE);
            const int kc = nk * 32;
            #pragma unroll
            for (int i = 0; i < 2; i++) CP_ASYNC16(aDst[i] + so, aSrc + kc + i * 8);
            #pragma unroll
            for (int i = 0; i < 2; i++) CP_ASYNC16(bDst[i] + so, bSrc + kc + i * 8);
        }
        CP_COMMIT();

        const uint32_t so = (uint32_t)((kt & (VNSTAGE - 1)) * V_STAGE);
        const uint32_t aB = aWarp + so;
        const uint32_t bB = bWarp + so;

        #pragma unroll
        for (int ksp = 0; ksp < 2; ksp++) {
            uint32_t af[2][4];
            #pragma unroll
            for (int mt = 0; mt < 2; mt++)
                LDSM_X4(af[mt][0], af[mt][1], af[mt][2], af[mt][3],
                        aB + (uint32_t)(mt * 1024) + cswk[ksp]);
            uint32_t bf[8][2];
            #pragma unroll
            for (int ntp = 0; ntp < 4; ntp++) {
                uint32_t q0, q1, q2, q3;
                LDSM_X4(q0, q1, q2, q3, bB + (uint32_t)(ntp * 1024) + cswk[ksp]);
                bf[2 * ntp    ][0] = q0; bf[2 * ntp    ][1] = q2;
                bf[2 * ntp + 1][0] = q1; bf[2 * ntp + 1][1] = q3;
            }
            #pragma unroll
            for (int mt = 0; mt < 2; mt++)
                #pragma unroll
                for (int nt = 0; nt < 8; nt++)
                    mma_f16(acc[mt][nt], af[mt], bf[nt]);
        }
        __syncthreads();
    }
    CP_WAIT0();

    // epilogue: + bias, fp16 store to V[o][n]
    #pragma unroll
    for (int mt = 0; mt < 2; mt++) {
        const int row0 = o0 + wm * 32 + mt * 16 + grp;
        const float b0 = __ldg(&bv[row0]);
        const float b8 = __ldg(&bv[row0 + 8]);
        #pragma unroll
        for (int nt = 0; nt < 8; nt++) {
            const int col = n0 + wn * 64 + nt * 8 + tig * 2;
            __half2 h0 = __floats2half2_rn(acc[mt][nt][0] + b0, acc[mt][nt][1] + b0);
            __half2 h8 = __floats2half2_rn(acc[mt][nt][2] + b8, acc[mt][nt][3] + b8);
            *(uint32_t*)&V[(size_t)row0 * NPIX + col]       = *(uint32_t*)&h0;
            *(uint32_t*)&V[(size_t)(row0 + 8) * NPIX + col] = *(uint32_t*)&h8;
        }
    }
}

// ===========================================================================
// Kernel 3: single-pass energy -> p = exp(e)/16 (fp16, unnormalized) + row inv.
// ===========================================================================
__global__ __launch_bounds__(256) void attn_p_kernel()
{
    __shared__ float ks[16][256];
    __shared__ float qs[16][32];

    const int n0   = blockIdx.x * 32;
    const int b    = blockIdx.y;
    const int tid  = threadIdx.x;
    const int lane = tid & 31;
    const int w    = tid >> 5;
    const int rb   = w * 4;

    const float* __restrict__ qb = g_q + (size_t)b * DQK * NPIX;
    const float* __restrict__ kb = g_k + (size_t)b * DQK * NPIX;
    __half* __restrict__ atth    = g_att_h + (size_t)b * NPIX * NPIX;

    for (int i = tid; i < 512; i += 256) {
        const int d = i >> 5, nl = i & 31;
        qs[d][nl] = qb[(size_t)d * NPIX + n0 + nl];
    }
    __syncthreads();
    float qr[4][16];
    #pragma unroll
    for (int rr = 0; rr < 4; rr++)
        #pragma unroll
        for (int d = 0; d < 16; d++)
            qr[rr][d] = qs[d][rb + rr];

    float sm[4] = {0.f, 0.f, 0.f, 0.f};

    for (int m0 = 0; m0 < NPIX; m0 += 256) {
        __syncthreads();
        #pragma unroll
        for (int r = 0; r < 4; r++) {
            const int lin = tid + 256 * r;
            const int d = lin >> 6, mm4 = (lin & 63) << 2;
            *(float4*)&ks[d][mm4] = *(const float4*)&kb[(size_t)d * NPIX + m0 + mm4];
        }
        __syncthreads();
        #pragma unroll
        for (int it = 0; it < 8; it++) {
            const int mm = lane + it * 32;
            float e0 = 0.f, e1 = 0.f, e2 = 0.f, e3 = 0.f;
            #pragma unroll
            for (int d = 0; d < 16; d++) {
                const float kv = ks[d][mm];
                e0 = fmaf(qr[0][d], kv, e0);
                e1 = fmaf(qr[1][d], kv, e1);
                e2 = fmaf(qr[2][d], kv, e2);
                e3 = fmaf(qr[3][d], kv, e3);
            }
            const float p0 = __expf(e0) * 0.0625f;
            const float p1 = __expf(e1) * 0.0625f;
            const float p2 = __expf(e2) * 0.0625f;
            const float p3 = __expf(e3) * 0.0625f;
            sm[0] += p0; sm[1] += p1; sm[2] += p2; sm[3] += p3;
            atth[(size_t)(n0 + rb + 0) * NPIX + m0 + mm] = __float2half_rn(p0);
            atth[(size_t)(n0 + rb + 1) * NPIX + m0 + mm] = __float2half_rn(p1);
            atth[(size_t)(n0 + rb + 2) * NPIX + m0 + mm] = __float2half_rn(p2);
            atth[(size_t)(n0 + rb + 3) * NPIX + m0 + mm] = __float2half_rn(p3);
        }
    }

    #pragma unroll
    for (int rr = 0; rr < 4; rr++) {
        float s = sm[rr];
        #pragma unroll
        for (int off = 16; off; off >>= 1)
            s += __shfl_xor_sync(0xffffffffu, s, off);
        if (lane == 0) g_inv[b * NPIX + n0 + rb + rr] = 1.f / s;
    }
}

// ===========================================================================
// Kernel 3b: att_norm — fp32 attention = fp16(p) * inv[row]. Memory-only.
// ===========================================================================
__global__ __launch_bounds__(256) void att_norm_kernel(float* __restrict__ att)
{
    const int b = blockIdx.z;
    const int n = blockIdx.y;
    const int m0 = blockIdx.x * 2048 + threadIdx.x * 8;
    const float inv = g_inv[b * NPIX + n];
    const __half* __restrict__ src = g_att_h + ((size_t)b * NPIX + n) * NPIX + m0;
    float* __restrict__ dst = att + ((size_t)b * NPIX + n) * NPIX + m0;

    const uint4 raw = *(const uint4*)src;
    const __half2* h2 = (const __half2*)&raw;
    float4 o0, o1;
    float2 t;
    t = __half22float2(h2[0]); o0.x = t.x * inv; o0.y = t.y * inv;
    t = __half22float2(h2[1]); o0.z = t.x * inv; o0.w = t.y * inv;
    t = __half22float2(h2[2]); o1.x = t.x * inv; o1.y = t.y * inv;
    t = __half22float2(h2[3]); o1.z = t.x * inv; o1.w = t.y * inv;
    *(float4*)dst       = o0;
    *(float4*)(dst + 4) = o1;
}

// ===========================================================================
// Kernel 4: out-bmm via fp16 HMMA (128x128, 2 CTAs/SM); epilogue D*inv + x.
// ===========================================================================
#define HBM_ 128
#define HBN_ 128
#define HBK_ 32
#define H_A_BYTES (HBM_ * 64)
#define H_STAGE   ((HBM_ + HBN_) * 64)
#define HNSTAGE   4
#define HSMEM     (HNSTAGE * H_STAGE)

__global__ __launch_bounds__(256, 2) void out_gemm_h(
    const float* __restrict__ x1, const float* __restrict__ x2,
    float* __restrict__ out)
{
    extern __shared__ char smraw[];
    const uint32_t smb = smem_u32(smraw);

    const int tid  = threadIdx.x;
    const int wid  = tid >> 5;
    const int lane = tid & 31;
    const int grp  = lane >> 2;
    const int tig  = lane & 3;
    const int wm   = wid >> 1;
    const int wn   = wid & 1;

    const int which = blockIdx.z & 1;
    const int b     = blockIdx.z >> 1;
    const int n0    = blockIdx.x * HBN_;
    const int c0    = blockIdx.y * HBM_;

    const __half* __restrict__ Vb = g_v_h[which] + (size_t)b * CH * NPIX;
    const __half* __restrict__ Ah = g_att_h + (size_t)b * NPIX * NPIX;

    const int a_row = tid >> 1;
    const int a_j0  = (tid & 1) * 2;
    const int a_sw  = (a_row >> 1) & 3;
    uint32_t aDst[2];
    #pragma unroll
    for (int i = 0; i < 2; i++)
        aDst[i] = smb + (uint32_t)(a_row * 64 + (((a_j0 + i) ^ a_sw) * 16));
    const __half* aSrc = Vb + (size_t)(c0 + a_row) * NPIX + a_j0 * 8;
    uint32_t bDst[2];
    #pragma unroll
    for (int i = 0; i < 2; i++)
        bDst[i] = smb + (uint32_t)(H_A_BYTES + a_row * 64 + (((a_j0 + i) ^ a_sw) * 16));
    const __half* bSrc = Ah + (size_t)(n0 + a_row) * NPIX + a_j0 * 8;

    const int radd = lane & 15;
    const int jA   = lane >> 4;
    const int lsw  = (radd >> 1) & 3;
    const uint32_t rowOff = (uint32_t)radd * 64;
    uint32_t cswk[2];
    cswk[0] = (uint32_t)(((0 + jA) ^ lsw) * 16);
    cswk[1] = (uint32_t)(((2 + jA) ^ lsw) * 16);

    float acc[2][8][4];
    #pragma unroll
    for (int mt = 0; mt < 2; mt++)
        #pragma unroll
        for (int nt = 0; nt < 8; nt++)
            #pragma unroll
            for (int q = 0; q < 4; q++) acc[mt][nt][q] = 0.f;

    const int KT = NPIX / HBK_;

    #pragma unroll
    for (int s = 0; s < HNSTAGE - 1; s++) {
        const uint32_t so = (uint32_t)(s * H_STAGE);
        const int kc = s * HBK_;
        #pragma unroll
        for (int i = 0; i < 2; i++) CP_ASYNC16(aDst[i] + so, aSrc + kc + i * 8);
        #pragma unroll
        for (int i = 0; i < 2; i++) CP_ASYNC16(bDst[i] + so, bSrc + kc + i * 8);
        CP_COMMIT();
    }

    const uint32_t aWarp = smb + (uint32_t)(wm * 32) * 64 + rowOff;
    const uint32_t bWarp = smb + H_A_BYTES + (uint32_t)(wn * 64) * 64 + rowOff;

    for (int kt = 0; kt < KT; kt++) {
        CP_WAIT2();
        __syncthreads();

        const int nk = kt + HNSTAGE - 1;
        if (nk < KT) {
            const uint32_t so = (uint32_t)((nk & (HNSTAGE - 1)) * H_STAGE);
            const int kc = nk * HBK_;
            #pragma unroll
            for (int i = 0; i < 2; i++) CP_ASYNC16(aDst[i] + so, aSrc + kc + i * 8);
            #pragma unroll
            for (int i = 0; i < 2; i++) CP_ASYNC16(bDst[i] + so, bSrc + kc + i * 8);
        }
        CP_COMMIT();

        const uint32_t so = (uint32_t)((kt & (HNSTAGE - 1)) * H_STAGE);
        const uint32_t aB = aWarp + so;
        const uint32_t bB = bWarp + so;

        #pragma unroll
        for (int ksp = 0; ksp < 2; ksp++) {
            uint32_t af[2][4];
            #pragma unroll
            for (int mt = 0; mt < 2; mt++)
                LDSM_X4(af[mt][0], af[mt][1], af[mt][2], af[mt][3],
                        aB + (uint32_t)(mt * 1024) + cswk[ksp]);
            uint32_t bf[8][2];
            #pragma unroll
            for (int ntp = 0; ntp < 4; ntp++) {
                uint32_t q0, q1, q2, q3;
                LDSM_X4(q0, q1, q2, q3, bB + (uint32_t)(ntp * 1024) + cswk[ksp]);
                bf[2 * ntp    ][0] = q0; bf[2 * ntp    ][1] = q2;
                bf[2 * ntp + 1][0] = q1; bf[2 * ntp + 1][1] = q3;
            }
            #pragma unroll
            for (int mt = 0; mt < 2; mt++)
                #pragma unroll
                for (int nt = 0; nt < 8; nt++)
                    mma_f16(acc[mt][nt], af[mt], bf[nt]);
        }
        __syncthreads();
    }
    CP_WAIT0();

    // epilogue: D*inv[n] + x
    const float* __restrict__ Xb = (which ? x2 : x1) + (size_t)b * CH * NPIX;
    float* __restrict__ Ob = out + (size_t)which * BATCH * CH * NPIX + (size_t)b * CH * NPIX;
    const float* __restrict__ invb = g_inv + (size_t)b * NPIX;

    #pragma unroll
    for (int mt = 0; mt < 2; mt++) {
        const int row0 = c0 + wm * 32 + mt * 16 + grp;
        const size_t r0b = (size_t)row0 * NPIX;
        const size_t r1b = (size_t)(row0 + 8) * NPIX;
        #pragma unroll
        for (int nt = 0; nt < 8; nt++) {
            const int col = n0 + wn * 64 + nt * 8 + tig * 2;
            const float2 iv = *(const float2*)&invb[col];
            const float2 x0 = *(const float2*)&Xb[r0b + col];
            const float2 x1v = *(const float2*)&Xb[r1b + col];
            float2 o0, o1;
            o0.x = fmaf(acc[mt][nt][0], iv.x, x0.x);
            o0.y = fmaf(acc[mt][nt][1], iv.y, x0.y);
            o1.x = fmaf(acc[mt][nt][2], iv.x, x1v.x);
            o1.y = fmaf(acc[mt][nt][3], iv.y, x1v.y);
            *(float2*)&Ob[r0b + col] = o0;
            *(float2*)&Ob[r1b + col] = o1;
        }
    }
}

// ===========================================================================
// launch
// ===========================================================================
extern "C" void kernel_launch(void* const* d_in, const int* in_sizes, int n_in,
                              void* d_out, int out_size)
{
    (void)in_sizes; (void)n_in; (void)out_size;
    const float* x1  = (const float*)d_in[0];
    const float* x2  = (const float*)d_in[1];
    const float* Wq  = (const float*)d_in[2];
    const float* bq  = (const float*)d_in[3];
    const float* Wk  = (const float*)d_in[4];
    const float* bk  = (const float*)d_in[5];
    const float* Wv1 = (const float*)d_in[6];
    const float* bv1 = (const float*)d_in[7];
    const float* Wv2 = (const float*)d_in[8];
    const float* bv2 = (const float*)d_in[9];

    float* out = (float*)d_out;
    float* att = out + (size_t)2 * BATCH * CH * NPIX;

    cudaFuncSetAttribute(out_gemm_h, cudaFuncAttributeMaxDynamicSharedMemorySize, HSMEM);
    cudaFuncSetAttribute(v_gemm_h, cudaFuncAttributeMaxDynamicSharedMemorySize, VSMEM);

    wconv_kernel<<<dim3(CH * CH / 1024, 2), 256>>>(Wv1, Wv2);
    xtrans_kernel<<<dim3(NPIX / 32, CH / 32, BATCH * 2), 256>>>(x1, x2);
    qk_kernel<<<dim3(NPIX / 32, BATCH), 256>>>(x1, x2, Wq, bq, Wk, bk);
    v_gemm_h<<<dim3(NPIX / 128, CH / 128, BATCH * 2), 256, VSMEM>>>(bv1, bv2);
    attn_p_kernel<<<dim3(NPIX / 32, BATCH), 256>>>();
    att_norm_kernel<<<dim3(2, NPIX, BATCH), 256>>>(att);
    out_gemm_h<<<dim3(NPIX / HBN_, CH / HBM_, BATCH * 2), 256, HSMEM>>>(x1, x2, out);
}